// round 14
// baseline (speedup 1.0000x reference)
#include <cuda_runtime.h>
#include <cuda_fp16.h>
#include <cstdint>

#define HID    1024
#define SEQ    1024
#define BATCH  4
#define NHEADS 16
#define DH     64
#define MROWS  (SEQ * BATCH)      // 4096
#define BHTOT  (BATCH * NHEADS)   // 64

// ---------------------------------------------------------------------------
// Device scratch (static -> allocation-guard safe). fp16 copies.
// Q/K/V row-major (m, n): m = s*BATCH+b, n = h*64+d
// ---------------------------------------------------------------------------
__device__ __align__(16) __half g_x[MROWS * HID];
__device__ __align__(16) __half g_w[3 * HID * HID];
__device__ __align__(16) __half g_q[MROWS * HID];
__device__ __align__(16) __half g_k[MROWS * HID];
__device__ __align__(16) __half g_v[MROWS * HID];

// ---------------------------------------------------------------------------
// Helpers
// ---------------------------------------------------------------------------
__device__ __forceinline__ void mma16816(float* d, const uint32_t* a,
                                         const uint32_t* b) {
    asm volatile(
        "mma.sync.aligned.m16n8k16.row.col.f32.f16.f16.f32 "
        "{%0,%1,%2,%3}, {%4,%5,%6,%7}, {%8,%9}, {%0,%1,%2,%3};"
        : "+f"(d[0]), "+f"(d[1]), "+f"(d[2]), "+f"(d[3])
        : "r"(a[0]), "r"(a[1]), "r"(a[2]), "r"(a[3]),
          "r"(b[0]), "r"(b[1]));
}

__device__ __forceinline__ uint32_t h2pack(float x, float y) {
    __half2 t = __float22half2_rn(make_float2(x, y));
    return *(uint32_t*)&t;
}
__device__ __forceinline__ uint32_t smem_u32(const void* p) {
    uint32_t a;
    asm("{ .reg .u64 t; cvta.to.shared.u64 t, %1; cvt.u32.u64 %0, t; }"
        : "=r"(a) : "l"(p));
    return a;
}
#define CP16(dst, src) \
    asm volatile("cp.async.cg.shared.global [%0], [%1], 16;" \
                 :: "r"(dst), "l"(src) : "memory")
#define CP_COMMIT() asm volatile("cp.async.commit_group;" ::: "memory")
#define CP_WAIT1()  asm volatile("cp.async.wait_group 1;" ::: "memory")
#define CP_WAIT0()  asm volatile("cp.async.wait_group 0;" ::: "memory")

// ---------------------------------------------------------------------------
// Fused convert: fp32 -> fp16 for X, Wq, Wk, Wv. Static block partition
// (measured 8.7us): blocks [0,1024) -> X, then 256 blocks per W.
// ---------------------------------------------------------------------------
__global__ void split_all(const float4* __restrict__ X,
                          const float4* __restrict__ Wq,
                          const float4* __restrict__ Wk,
                          const float4* __restrict__ Wv)
{
    const int bidx = blockIdx.x;
    const float4* src;
    __half* dst;
    int base;
    if (bidx < 1024) {
        src = X; dst = g_x; base = bidx * 1024;
    } else {
        const int r   = (bidx - 1024) >> 8;
        const int off = (bidx - 1024) & 255;
        src = (r == 0) ? Wq : (r == 1) ? Wk : Wv;
        dst = g_w + (size_t)r * HID * HID;
        base = off * 1024;
    }
    const int i0 = base + threadIdx.x;
    #pragma unroll
    for (int u = 0; u < 4; u++) {
        const int i = i0 + u * 256;
        float4 v = src[i];
        uint2 hv;
        hv.x = h2pack(v.x, v.y);
        hv.y = h2pack(v.z, v.w);
        ((uint2*)dst)[i] = hv;
    }
}

// ---------------------------------------------------------------------------
// fp16 GEMM via mma.sync, cp.async double-buffered (K-chunk 64, 2 stages).
// Same MMA order as R12 -> bit-identical output. 2 CTAs/SM preserved
// (2 x 72KB smem = 144KB < 228KB; regs unconstrained).
// grid = (HID/128, MROWS/128, 3), block = 256.
// ---------------------------------------------------------------------------
#define GROWW  36                      // words per smem row (72 halves)
#define GTILE  (128 * GROWW)           // 4608 words per tile
#define GSTG   (2 * GTILE)             // 9216 words per stage (A+B)
#define GEMM_SMEM (2 * GSTG * 4)       // 73728 B

__global__ __launch_bounds__(256) void gemm_kernel(
    const float* __restrict__ b0,
    const float* __restrict__ b1,
    const float* __restrict__ b2)
{
    extern __shared__ __align__(16) uint32_t smw[];
    const uint32_t smem_base = smem_u32(smw);

    const int tid  = threadIdx.x;
    const int wid  = tid >> 5;
    const int lane = tid & 31;
    const int g    = lane >> 2;
    const int cq   = lane & 3;

    const int n0 = blockIdx.x * 128;
    const int m0 = blockIdx.y * 128;
    const int z  = blockIdx.z;

    const __half* W = g_w + (size_t)z * HID * HID;
    const float* bias = (z == 0) ? b0 : (z == 1) ? b1 : b2;
    __half* dst = (z == 0) ? g_q : (z == 1) ? g_k : g_v;

    const int wm = (wid & 3) * 32;
    const int wn = (wid >> 2) * 64;

    float acc[2][8][4];
    #pragma unroll
    for (int mi = 0; mi < 2; mi++)
        #pragma unroll
        for (int nj = 0; nj < 8; nj++)
            #pragma unroll
            for (int r = 0; r < 4; r++) acc[mi][nj][r] = 0.f;

    // cp.async loader: 2 threads/row, each 32 halves (4x16B) per tile
    const int crow = tid >> 1;
    const int cseg = tid & 1;

    auto issue = [&](int s, int k0) {
        const size_t aofs = (size_t)(m0 + crow) * HID + k0 + cseg * 32;
        const size_t bofs = (size_t)(n0 + crow) * HID + k0 + cseg * 32;
        const uint32_t ad = smem_base + (s * GSTG + crow * GROWW + cseg * 16) * 4;
        const uint32_t bd = ad + GTILE * 4;
        #pragma unroll
        for (int j = 0; j < 4; j++) {
            CP16(ad + j * 16, g_x + aofs + j * 8);
            CP16(bd + j * 16, W + bofs + j * 8);
        }
    };

    issue(0, 0);
    CP_COMMIT();

    for (int c = 0; c < HID / 64; c++) {          // 16 iterations
        const int s = c & 1;
        if (c + 1 < HID / 64) { issue(s ^ 1, (c + 1) * 64); CP_COMMIT(); CP_WAIT1(); }
        else                  { CP_WAIT0(); }
        __syncthreads();                          // stage s visible to all

        const int sb = s * GSTG;
        #pragma unroll
        for (int ks = 0; ks < 4; ks++) {
            uint32_t ah[2][4];
            #pragma unroll
            for (int mi = 0; mi < 2; mi++) {
                const int base = sb + (wm + mi * 16 + g) * GROWW + ks * 8 + cq;
                ah[mi][0] = smw[base];
                ah[mi][1] = smw[base + 8 * GROWW];
                ah[mi][2] = smw[base + 4];
                ah[mi][3] = smw[base + 8 * GROWW + 4];
            }
            #pragma unroll
            for (int nj = 0; nj < 8; nj++) {
                const int bbase = sb + GTILE + (wn + nj * 8 + g) * GROWW + ks * 8 + cq;
                uint32_t bh[2];
                bh[0] = smw[bbase];
                bh[1] = smw[bbase + 4];
                #pragma unroll
                for (int mi = 0; mi < 2; mi++)
                    mma16816(acc[mi][nj], ah[mi], bh);
            }
        }
        __syncthreads();                          // stage s consumed
    }

    // Epilogue: add bias, convert to fp16
    #pragma unroll
    for (int mi = 0; mi < 2; mi++) {
        const int r0 = m0 + wm + mi * 16 + g;
        #pragma unroll
        for (int nj = 0; nj < 8; nj++) {
            const int col = n0 + wn + nj * 8 + cq * 2;
            const float bz0 = __ldg(&bias[col]);
            const float bz1 = __ldg(&bias[col + 1]);
            *(uint32_t*)&dst[(size_t)r0 * HID + col] =
                h2pack(acc[mi][nj][0] + bz0, acc[mi][nj][1] + bz1);
            *(uint32_t*)&dst[(size_t)(r0 + 8) * HID + col] =
                h2pack(acc[mi][nj][2] + bz0, acc[mi][nj][3] + bz1);
        }
    }
}

// ---------------------------------------------------------------------------
// fp16 tensor-core flash attention. (R12 exact — best measured.)
// grid = (SEQ/128, B*H), block = 256 (8 warps, 16 query rows each).
// ---------------------------------------------------------------------------
#define KROWW  36                          // words per K row (72 halves)
#define KTILE_W (128 * KROWW)              // 4608 words
#define VROWW  68                          // words per Vt row (136 halves)
#define VT_OFF KTILE_W
#define ATTN_SMEM ((KTILE_W + 64 * VROWW) * 4)   // 35840 B

__global__ __launch_bounds__(256) void attn_kernel(
    const float* __restrict__ mask, float* __restrict__ out)
{
    extern __shared__ __align__(16) uint32_t smw[];
    uint16_t* smh = (uint16_t*)smw;

    const int tid  = threadIdx.x;
    const int wid  = tid >> 5;
    const int lane = tid & 31;
    const int g    = lane >> 2;
    const int cq   = lane & 3;
    const int bh   = blockIdx.y;
    const int b    = bh >> 4;
    const int h    = bh & 15;
    const int q0   = blockIdx.x * 128;

    const int lrow = tid >> 3;
    const int lcol = (tid & 7) * 8;

    // ---- Stage Q (128x64) through K region; keep fragments in registers
    #pragma unroll
    for (int rr = 0; rr < 128; rr += 32) {
        const int r = rr + lrow;
        const size_t off = ((size_t)(q0 + r) * BATCH + b) * HID + h * DH + lcol;
        *(uint4*)(smh + r * 72 + lcol) = *(const uint4*)(g_q + off);
    }
    __syncthreads();

    uint32_t qh[4][4];
    #pragma unroll
    for (int ks = 0; ks < 4; ks++) {
        const int base = (wid * 16 + g) * KROWW + ks * 8 + cq;
        qh[ks][0] = smw[base];
        qh[ks][1] = smw[base + 8 * KROWW];
        qh[ks][2] = smw[base + 4];
        qh[ks][3] = smw[base + 8 * KROWW + 4];
    }

    float m0 = -1e30f, m1 = -1e30f, l0 = 0.f, l1 = 0.f;
    float oacc[8][4];
    #pragma unroll
    for (int j = 0; j < 8; j++)
        #pragma unroll
        for (int r = 0; r < 4; r++) oacc[j][r] = 0.f;

    const float scale = 0.125f;           // 1/sqrt(64)
    const int r0 = q0 + wid * 16 + g;     // query rows r0, r0+8
    const float* mrow0 = mask + (size_t)b * SEQ * SEQ + (size_t)r0 * SEQ;
    const float* mrow1 = mrow0 + 8 * (size_t)SEQ;

    const int vp  = tid & 63;             // key pair (keys 2vp, 2vp+1)
    const int vd0 = (tid >> 6) * 16;      // 16 d-values per thread

    for (int k0 = 0; k0 < SEQ; k0 += 128) {
        __syncthreads();                  // previous S/PV readers done

        // --- K tile (128 keys x 64 d)
        #pragma unroll
        for (int rr = 0; rr < 128; rr += 32) {
            const int kk = rr + lrow;
            const size_t off = ((size_t)(k0 + kk) * BATCH + b) * HID + h * DH + lcol;
            *(uint4*)(smh + kk * 72 + lcol) = *(const uint4*)(g_k + off);
        }
        // --- V tile transposed: Vt[d][key]
        {
            const size_t ra = ((size_t)(k0 + 2 * vp) * BATCH + b) * HID + h * DH + vd0;
            const size_t rb = ra + BATCH * HID;
            uint4 a0 = *(const uint4*)(g_v + ra);
            uint4 a1 = *(const uint4*)(g_v + ra + 8);
            uint4 c0 = *(const uint4*)(g_v + rb);
            uint4 c1 = *(const uint4*)(g_v + rb + 8);
            const uint32_t wa[8] = {a0.x, a0.y, a0.z, a0.w, a1.x, a1.y, a1.z, a1.w};
            const uint32_t wb[8] = {c0.x, c0.y, c0.z, c0.w, c1.x, c1.y, c1.z, c1.w};
            #pragma unroll
            for (int j = 0; j < 8; j++) {
                smw[VT_OFF + (vd0 + 2 * j)     * VROWW + vp] = __byte_perm(wa[j], wb[j], 0x5410);
                smw[VT_OFF + (vd0 + 2 * j + 1) * VROWW + vp] = __byte_perm(wa[j], wb[j], 0x7632);
            }
        }
        __syncthreads();

        // --- S = Q K^T (16 n-tiles of 8 keys)
        float sa[16][4];
        #pragma unroll
        for (int nt = 0; nt < 16; nt++) {
            sa[nt][0] = 0.f; sa[nt][1] = 0.f; sa[nt][2] = 0.f; sa[nt][3] = 0.f;
            #pragma unroll
            for (int ks = 0; ks < 4; ks++) {
                const int ba = (nt * 8 + g) * KROWW + ks * 8 + cq;
                uint32_t bf[2];
                bf[0] = smw[ba];
                bf[1] = smw[ba + 4];
                mma16816(sa[nt], qh[ks], bf);
            }
        }

        // --- scale + mask + row max
        float nx0 = -1e30f, nx1 = -1e30f;
        #pragma unroll
        for (int nt = 0; nt < 16; nt++) {
            const float2 mv0 = *(const float2*)&mrow0[k0 + nt * 8 + 2 * cq];
            const float2 mv1 = *(const float2*)&mrow1[k0 + nt * 8 + 2 * cq];
            sa[nt][0] = fmaf(sa[nt][0], scale, mv0.x);
            sa[nt][1] = fmaf(sa[nt][1], scale, mv0.y);
            sa[nt][2] = fmaf(sa[nt][2], scale, mv1.x);
            sa[nt][3] = fmaf(sa[nt][3], scale, mv1.y);
            nx0 = fmaxf(nx0, fmaxf(sa[nt][0], sa[nt][1]));
            nx1 = fmaxf(nx1, fmaxf(sa[nt][2], sa[nt][3]));
        }
        nx0 = fmaxf(nx0, __shfl_xor_sync(0xffffffffu, nx0, 1));
        nx0 = fmaxf(nx0, __shfl_xor_sync(0xffffffffu, nx0, 2));
        nx1 = fmaxf(nx1, __shfl_xor_sync(0xffffffffu, nx1, 1));
        nx1 = fmaxf(nx1, __shfl_xor_sync(0xffffffffu, nx1, 2));

        const float mn0 = fmaxf(m0, nx0), mn1 = fmaxf(m1, nx1);
        const float c0s = __expf(m0 - mn0), c1s = __expf(m1 - mn1);
        m0 = mn0; m1 = mn1;
        l0 *= c0s; l1 *= c1s;
        #pragma unroll
        for (int j = 0; j < 8; j++) {
            oacc[j][0] *= c0s; oacc[j][1] *= c0s;
            oacc[j][2] *= c1s; oacc[j][3] *= c1s;
        }

        // --- P (fp16) and PV, per 16-key k-step
        #pragma unroll
        for (int kt = 0; kt < 8; kt++) {
            const float p00 = __expf(sa[2 * kt][0] - m0);
            const float p01 = __expf(sa[2 * kt][1] - m0);
            const float p10 = __expf(sa[2 * kt][2] - m1);
            const float p11 = __expf(sa[2 * kt][3] - m1);
            const float p20 = __expf(sa[2 * kt + 1][0] - m0);
            const float p21 = __expf(sa[2 * kt + 1][1] - m0);
            const float p30 = __expf(sa[2 * kt + 1][2] - m1);
            const float p31 = __expf(sa[2 * kt + 1][3] - m1);
            l0 += p00 + p01 + p20 + p21;
            l1 += p10 + p11 + p30 + p31;

            uint32_t pa[4];
            pa[0] = h2pack(p00, p01);
            pa[1] = h2pack(p10, p11);
            pa[2] = h2pack(p20, p21);
            pa[3] = h2pack(p30, p31);

            #pragma unroll
            for (int nt2 = 0; nt2 < 8; nt2++) {
                const int ba = VT_OFF + (nt2 * 8 + g) * VROWW + kt * 8 + cq;
                uint32_t vf[2];
                vf[0] = smw[ba];
                vf[1] = smw[ba + 4];
                mma16816(oacc[nt2], pa, vf);
            }
        }
    }

    // --- reduce l across the 4 lanes per row, normalize, store (S,B,HID)
    l0 += __shfl_xor_sync(0xffffffffu, l0, 1);
    l0 += __shfl_xor_sync(0xffffffffu, l0, 2);
    l1 += __shfl_xor_sync(0xffffffffu, l1, 1);
    l1 += __shfl_xor_sync(0xffffffffu, l1, 2);
    const float i0 = 1.0f / l0, i1 = 1.0f / l1;

    #pragma unroll
    for (int nt2 = 0; nt2 < 8; nt2++) {
        const int col = h * DH + nt2 * 8 + 2 * cq;
        const size_t o0 = (size_t)r0 * (BATCH * HID) + (size_t)b * HID + col;
        const size_t o1 = o0 + 8 * (size_t)(BATCH * HID);
        float2 v0, v1;
        v0.x = oacc[nt2][0] * i0; v0.y = oacc[nt2][1] * i0;
        v1.x = oacc[nt2][2] * i1; v1.y = oacc[nt2][3] * i1;
        *(float2*)&out[o0] = v0;
        *(float2*)&out[o1] = v1;
    }
}

// ---------------------------------------------------------------------------
// Launch
// ---------------------------------------------------------------------------
extern "C" void kernel_launch(void* const* d_in, const int* in_sizes, int n_in,
                              void* d_out, int out_size)
{
    const float* X    = (const float*)d_in[0];
    const float* mask = (const float*)d_in[1];
    const float* Wq   = (const float*)d_in[2];
    const float* bq   = (const float*)d_in[3];
    const float* Wk   = (const float*)d_in[4];
    const float* bk   = (const float*)d_in[5];
    const float* Wv   = (const float*)d_in[6];
    const float* bv   = (const float*)d_in[7];
    float* out = (float*)d_out;

    split_all<<<1792, 256>>>((const float4*)X, (const float4*)Wq,
                             (const float4*)Wk, (const float4*)Wv);

    cudaFuncSetAttribute(gemm_kernel,
                         cudaFuncAttributeMaxDynamicSharedMemorySize, GEMM_SMEM);
    dim3 ggrid(HID / 128, MROWS / 128, 3);
    gemm_kernel<<<ggrid, 256, GEMM_SMEM>>>(bq, bk, bv);

    cudaFuncSetAttribute(attn_kernel,
                         cudaFuncAttributeMaxDynamicSharedMemorySize, ATTN_SMEM);
    dim3 agrid(SEQ / 128, BHTOT);
    attn_kernel<<<agrid, 256, ATTN_SMEM>>>(mask, out);
}

// round 15
// speedup vs baseline: 1.1489x; 1.1489x over previous
#include <cuda_runtime.h>
#include <cuda_fp16.h>
#include <cstdint>

#define HID    1024
#define SEQ    1024
#define BATCH  4
#define NHEADS 16
#define DH     64
#define MROWS  (SEQ * BATCH)      // 4096
#define BHTOT  (BATCH * NHEADS)   // 64

// ---------------------------------------------------------------------------
// Device scratch (static -> allocation-guard safe). fp16 copies.
// Q/K/V row-major (m, n): m = s*BATCH+b, n = h*64+d
// ---------------------------------------------------------------------------
__device__ __align__(16) __half g_x[MROWS * HID];
__device__ __align__(16) __half g_w[3 * HID * HID];
__device__ __align__(16) __half g_q[MROWS * HID];
__device__ __align__(16) __half g_k[MROWS * HID];
__device__ __align__(16) __half g_v[MROWS * HID];

// ---------------------------------------------------------------------------
// Helpers
// ---------------------------------------------------------------------------
__device__ __forceinline__ void mma16816(float* d, const uint32_t* a,
                                         const uint32_t* b) {
    asm volatile(
        "mma.sync.aligned.m16n8k16.row.col.f32.f16.f16.f32 "
        "{%0,%1,%2,%3}, {%4,%5,%6,%7}, {%8,%9}, {%0,%1,%2,%3};"
        : "+f"(d[0]), "+f"(d[1]), "+f"(d[2]), "+f"(d[3])
        : "r"(a[0]), "r"(a[1]), "r"(a[2]), "r"(a[3]),
          "r"(b[0]), "r"(b[1]));
}

__device__ __forceinline__ uint32_t h2pack(float x, float y) {
    __half2 t = __float22half2_rn(make_float2(x, y));
    return *(uint32_t*)&t;
}

// ---------------------------------------------------------------------------
// Fused convert: fp32 -> fp16 for X, Wq, Wk, Wv. Static block partition
// (measured 8.7us): blocks [0,1024) -> X, then 256 blocks per W.
// ---------------------------------------------------------------------------
__global__ void split_all(const float4* __restrict__ X,
                          const float4* __restrict__ Wq,
                          const float4* __restrict__ Wk,
                          const float4* __restrict__ Wv)
{
    const int bidx = blockIdx.x;
    const float4* src;
    __half* dst;
    int base;
    if (bidx < 1024) {
        src = X; dst = g_x; base = bidx * 1024;
    } else {
        const int r   = (bidx - 1024) >> 8;
        const int off = (bidx - 1024) & 255;
        src = (r == 0) ? Wq : (r == 1) ? Wk : Wv;
        dst = g_w + (size_t)r * HID * HID;
        base = off * 1024;
    }
    const int i0 = base + threadIdx.x;
    #pragma unroll
    for (int u = 0; u < 4; u++) {
        const int i = i0 + u * 256;
        float4 v = src[i];
        uint2 hv;
        hv.x = h2pack(v.x, v.y);
        hv.y = h2pack(v.z, v.w);
        ((uint2*)dst)[i] = hv;
    }
}

// ---------------------------------------------------------------------------
// fp16 GEMM via mma.sync: C[m][n] = X[m][:] . W[n][:] + bias[n] -> fp16.
// CTA tile 128x128, 8 warps (32M x 64N each), K-chunk 64, serialized loads
// (cross-CTA overlap at 2 CTAs/SM; beats cp.async per R7/R10/R14 evidence).
// grid = (HID/128, MROWS/128, 3), block = 256.
// ---------------------------------------------------------------------------
#define TROW   72                      // halves per smem row (64 data + 8 pad)
#define TWORDS (128 * (TROW / 2))      // 4608 words per tile
#define GEMM_SMEM (2 * 128 * TROW * 2) // 36864 B

__global__ __launch_bounds__(256) void gemm_kernel(
    const float* __restrict__ b0,
    const float* __restrict__ b1,
    const float* __restrict__ b2)
{
    extern __shared__ __align__(16) __half sm[];
    __half* tA = sm;
    __half* tB = sm + 128 * TROW;
    const uint32_t* smw = (const uint32_t*)sm;

    const int tid  = threadIdx.x;
    const int wid  = tid >> 5;
    const int lane = tid & 31;
    const int g    = lane >> 2;
    const int cq   = lane & 3;

    const int n0 = blockIdx.x * 128;
    const int m0 = blockIdx.y * 128;
    const int z  = blockIdx.z;

    const __half* W = g_w + (size_t)z * HID * HID;
    const float* bias = (z == 0) ? b0 : (z == 1) ? b1 : b2;
    __half* dst = (z == 0) ? g_q : (z == 1) ? g_k : g_v;

    const int wm = (wid & 3) * 32;
    const int wn = (wid >> 2) * 64;

    float acc[2][8][4];
    #pragma unroll
    for (int mi = 0; mi < 2; mi++)
        #pragma unroll
        for (int nj = 0; nj < 8; nj++)
            #pragma unroll
            for (int r = 0; r < 4; r++) acc[mi][nj][r] = 0.f;

    const int lrow = tid >> 3;            // 0..31 (row within pass)
    const int lcol = (tid & 7) * 8;       // half offset within row

    for (int c = 0; c < HID / 64; c++) {
        const int k0 = c * 64;
        #pragma unroll
        for (int rr = 0; rr < 128; rr += 32) {
            const int row = rr + lrow;
            *(float4*)&tA[row * TROW + lcol] =
                *(const float4*)&g_x[(size_t)(m0 + row) * HID + k0 + lcol];
            *(float4*)&tB[row * TROW + lcol] =
                *(const float4*)&W[(size_t)(n0 + row) * HID + k0 + lcol];
        }
        __syncthreads();

        #pragma unroll
        for (int ks = 0; ks < 4; ks++) {
            uint32_t ah[2][4];
            #pragma unroll
            for (int mi = 0; mi < 2; mi++) {
                const int base = (wm + mi * 16 + g) * (TROW / 2) + ks * 8 + cq;
                ah[mi][0] = smw[base];
                ah[mi][1] = smw[base + 8 * (TROW / 2)];
                ah[mi][2] = smw[base + 4];
                ah[mi][3] = smw[base + 8 * (TROW / 2) + 4];
            }
            #pragma unroll
            for (int nj = 0; nj < 8; nj++) {
                const int bbase = TWORDS + (wn + nj * 8 + g) * (TROW / 2) + ks * 8 + cq;
                uint32_t bh[2];
                bh[0] = smw[bbase];
                bh[1] = smw[bbase + 4];
                #pragma unroll
                for (int mi = 0; mi < 2; mi++)
                    mma16816(acc[mi][nj], ah[mi], bh);
            }
        }
        __syncthreads();
    }

    // Epilogue: add bias, convert to fp16
    #pragma unroll
    for (int mi = 0; mi < 2; mi++) {
        const int r0 = m0 + wm + mi * 16 + g;
        #pragma unroll
        for (int nj = 0; nj < 8; nj++) {
            const int col = n0 + wn + nj * 8 + cq * 2;
            const float bz0 = __ldg(&bias[col]);
            const float bz1 = __ldg(&bias[col + 1]);
            *(uint32_t*)&dst[(size_t)r0 * HID + col] =
                h2pack(acc[mi][nj][0] + bz0, acc[mi][nj][1] + bz1);
            *(uint32_t*)&dst[(size_t)(r0 + 8) * HID + col] =
                h2pack(acc[mi][nj][2] + bz0, acc[mi][nj][3] + bz1);
        }
    }
}

// ---------------------------------------------------------------------------
// fp16 tensor-core flash attention. (Verified best configuration.)
// grid = (SEQ/128, B*H), block = 256 (8 warps, 16 query rows each).
// ---------------------------------------------------------------------------
#define KROWW  36                          // words per K row (72 halves)
#define KTILE_W (128 * KROWW)              // 4608 words
#define VROWW  68                          // words per Vt row (136 halves)
#define VT_OFF KTILE_W
#define ATTN_SMEM ((KTILE_W + 64 * VROWW) * 4)   // 35840 B

__global__ __launch_bounds__(256) void attn_kernel(
    const float* __restrict__ mask, float* __restrict__ out)
{
    extern __shared__ __align__(16) uint32_t smw[];
    uint16_t* smh = (uint16_t*)smw;

    const int tid  = threadIdx.x;
    const int wid  = tid >> 5;
    const int lane = tid & 31;
    const int g    = lane >> 2;
    const int cq   = lane & 3;
    const int bh   = blockIdx.y;
    const int b    = bh >> 4;
    const int h    = bh & 15;
    const int q0   = blockIdx.x * 128;

    const int lrow = tid >> 3;
    const int lcol = (tid & 7) * 8;

    // ---- Stage Q (128x64) through K region; keep fragments in registers
    #pragma unroll
    for (int rr = 0; rr < 128; rr += 32) {
        const int r = rr + lrow;
        const size_t off = ((size_t)(q0 + r) * BATCH + b) * HID + h * DH + lcol;
        *(uint4*)(smh + r * 72 + lcol) = *(const uint4*)(g_q + off);
    }
    __syncthreads();

    uint32_t qh[4][4];
    #pragma unroll
    for (int ks = 0; ks < 4; ks++) {
        const int base = (wid * 16 + g) * KROWW + ks * 8 + cq;
        qh[ks][0] = smw[base];
        qh[ks][1] = smw[base + 8 * KROWW];
        qh[ks][2] = smw[base + 4];
        qh[ks][3] = smw[base + 8 * KROWW + 4];
    }

    float m0 = -1e30f, m1 = -1e30f, l0 = 0.f, l1 = 0.f;
    float oacc[8][4];
    #pragma unroll
    for (int j = 0; j < 8; j++)
        #pragma unroll
        for (int r = 0; r < 4; r++) oacc[j][r] = 0.f;

    const float scale = 0.125f;           // 1/sqrt(64)
    const int r0 = q0 + wid * 16 + g;     // query rows r0, r0+8
    const float* mrow0 = mask + (size_t)b * SEQ * SEQ + (size_t)r0 * SEQ;
    const float* mrow1 = mrow0 + 8 * (size_t)SEQ;

    const int vp  = tid & 63;             // key pair (keys 2vp, 2vp+1)
    const int vd0 = (tid >> 6) * 16;      // 16 d-values per thread

    for (int k0 = 0; k0 < SEQ; k0 += 128) {
        __syncthreads();                  // previous S/PV readers done

        // --- K tile (128 keys x 64 d)
        #pragma unroll
        for (int rr = 0; rr < 128; rr += 32) {
            const int kk = rr + lrow;
            const size_t off = ((size_t)(k0 + kk) * BATCH + b) * HID + h * DH + lcol;
            *(uint4*)(smh + kk * 72 + lcol) = *(const uint4*)(g_k + off);
        }
        // --- V tile transposed: Vt[d][key]
        {
            const size_t ra = ((size_t)(k0 + 2 * vp) * BATCH + b) * HID + h * DH + vd0;
            const size_t rb = ra + BATCH * HID;
            uint4 a0 = *(const uint4*)(g_v + ra);
            uint4 a1 = *(const uint4*)(g_v + ra + 8);
            uint4 c0 = *(const uint4*)(g_v + rb);
            uint4 c1 = *(const uint4*)(g_v + rb + 8);
            const uint32_t wa[8] = {a0.x, a0.y, a0.z, a0.w, a1.x, a1.y, a1.z, a1.w};
            const uint32_t wb[8] = {c0.x, c0.y, c0.z, c0.w, c1.x, c1.y, c1.z, c1.w};
            #pragma unroll
            for (int j = 0; j < 8; j++) {
                smw[VT_OFF + (vd0 + 2 * j)     * VROWW + vp] = __byte_perm(wa[j], wb[j], 0x5410);
                smw[VT_OFF + (vd0 + 2 * j + 1) * VROWW + vp] = __byte_perm(wa[j], wb[j], 0x7632);
            }
        }
        __syncthreads();

        // --- S = Q K^T (16 n-tiles of 8 keys)
        float sa[16][4];
        #pragma unroll
        for (int nt = 0; nt < 16; nt++) {
            sa[nt][0] = 0.f; sa[nt][1] = 0.f; sa[nt][2] = 0.f; sa[nt][3] = 0.f;
            #pragma unroll
            for (int ks = 0; ks < 4; ks++) {
                const int ba = (nt * 8 + g) * KROWW + ks * 8 + cq;
                uint32_t bf[2];
                bf[0] = smw[ba];
                bf[1] = smw[ba + 4];
                mma16816(sa[nt], qh[ks], bf);
            }
        }

        // --- scale + mask + row max
        float nx0 = -1e30f, nx1 = -1e30f;
        #pragma unroll
        for (int nt = 0; nt < 16; nt++) {
            const float2 mv0 = *(const float2*)&mrow0[k0 + nt * 8 + 2 * cq];
            const float2 mv1 = *(const float2*)&mrow1[k0 + nt * 8 + 2 * cq];
            sa[nt][0] = fmaf(sa[nt][0], scale, mv0.x);
            sa[nt][1] = fmaf(sa[nt][1], scale, mv0.y);
            sa[nt][2] = fmaf(sa[nt][2], scale, mv1.x);
            sa[nt][3] = fmaf(sa[nt][3], scale, mv1.y);
            nx0 = fmaxf(nx0, fmaxf(sa[nt][0], sa[nt][1]));
            nx1 = fmaxf(nx1, fmaxf(sa[nt][2], sa[nt][3]));
        }
        nx0 = fmaxf(nx0, __shfl_xor_sync(0xffffffffu, nx0, 1));
        nx0 = fmaxf(nx0, __shfl_xor_sync(0xffffffffu, nx0, 2));
        nx1 = fmaxf(nx1, __shfl_xor_sync(0xffffffffu, nx1, 1));
        nx1 = fmaxf(nx1, __shfl_xor_sync(0xffffffffu, nx1, 2));

        const float mn0 = fmaxf(m0, nx0), mn1 = fmaxf(m1, nx1);
        const float c0s = __expf(m0 - mn0), c1s = __expf(m1 - mn1);
        m0 = mn0; m1 = mn1;
        l0 *= c0s; l1 *= c1s;
        #pragma unroll
        for (int j = 0; j < 8; j++) {
            oacc[j][0] *= c0s; oacc[j][1] *= c0s;
            oacc[j][2] *= c1s; oacc[j][3] *= c1s;
        }

        // --- P (fp16) and PV, per 16-key k-step
        #pragma unroll
        for (int kt = 0; kt < 8; kt++) {
            const float p00 = __expf(sa[2 * kt][0] - m0);
            const float p01 = __expf(sa[2 * kt][1] - m0);
            const float p10 = __expf(sa[2 * kt][2] - m1);
            const float p11 = __expf(sa[2 * kt][3] - m1);
            const float p20 = __expf(sa[2 * kt + 1][0] - m0);
            const float p21 = __expf(sa[2 * kt + 1][1] - m0);
            const float p30 = __expf(sa[2 * kt + 1][2] - m1);
            const float p31 = __expf(sa[2 * kt + 1][3] - m1);
            l0 += p00 + p01 + p20 + p21;
            l1 += p10 + p11 + p30 + p31;

            uint32_t pa[4];
            pa[0] = h2pack(p00, p01);
            pa[1] = h2pack(p10, p11);
            pa[2] = h2pack(p20, p21);
            pa[3] = h2pack(p30, p31);

            #pragma unroll
            for (int nt2 = 0; nt2 < 8; nt2++) {
                const int ba = VT_OFF + (nt2 * 8 + g) * VROWW + kt * 8 + cq;
                uint32_t vf[2];
                vf[0] = smw[ba];
                vf[1] = smw[ba + 4];
                mma16816(oacc[nt2], pa, vf);
            }
        }
    }

    // --- reduce l across the 4 lanes per row, normalize, store (S,B,HID)
    l0 += __shfl_xor_sync(0xffffffffu, l0, 1);
    l0 += __shfl_xor_sync(0xffffffffu, l0, 2);
    l1 += __shfl_xor_sync(0xffffffffu, l1, 1);
    l1 += __shfl_xor_sync(0xffffffffu, l1, 2);
    const float i0 = 1.0f / l0, i1 = 1.0f / l1;

    #pragma unroll
    for (int nt2 = 0; nt2 < 8; nt2++) {
        const int col = h * DH + nt2 * 8 + 2 * cq;
        const size_t o0 = (size_t)r0 * (BATCH * HID) + (size_t)b * HID + col;
        const size_t o1 = o0 + 8 * (size_t)(BATCH * HID);
        float2 v0, v1;
        v0.x = oacc[nt2][0] * i0; v0.y = oacc[nt2][1] * i0;
        v1.x = oacc[nt2][2] * i1; v1.y = oacc[nt2][3] * i1;
        *(float2*)&out[o0] = v0;
        *(float2*)&out[o1] = v1;
    }
}

// ---------------------------------------------------------------------------
// Launch
// ---------------------------------------------------------------------------
extern "C" void kernel_launch(void* const* d_in, const int* in_sizes, int n_in,
                              void* d_out, int out_size)
{
    const float* X    = (const float*)d_in[0];
    const float* mask = (const float*)d_in[1];
    const float* Wq   = (const float*)d_in[2];
    const float* bq   = (const float*)d_in[3];
    const float* Wk   = (const float*)d_in[4];
    const float* bk   = (const float*)d_in[5];
    const float* Wv   = (const float*)d_in[6];
    const float* bv   = (const float*)d_in[7];
    float* out = (float*)d_out;

    split_all<<<1792, 256>>>((const float4*)X, (const float4*)Wq,
                             (const float4*)Wk, (const float4*)Wv);

    cudaFuncSetAttribute(gemm_kernel,
                         cudaFuncAttributeMaxDynamicSharedMemorySize, GEMM_SMEM);
    dim3 ggrid(HID / 128, MROWS / 128, 3);
    gemm_kernel<<<ggrid, 256, GEMM_SMEM>>>(bq, bk, bv);

    cudaFuncSetAttribute(attn_kernel,
                         cudaFuncAttributeMaxDynamicSharedMemorySize, ATTN_SMEM);
    dim3 agrid(SEQ / 128, BHTOT);
    attn_kernel<<<agrid, 256, ATTN_SMEM>>>(mask, out);
}

// round 16
// speedup vs baseline: 1.1609x; 1.0104x over previous
#include <cuda_runtime.h>
#include <cuda_fp16.h>
#include <cstdint>

#define HID    1024
#define SEQ    1024
#define BATCH  4
#define NHEADS 16
#define DH     64
#define MROWS  (SEQ * BATCH)      // 4096
#define BHTOT  (BATCH * NHEADS)   // 64

// ---------------------------------------------------------------------------
// Device scratch (static -> allocation-guard safe). fp16 copies.
// Q/K/V row-major (m, n): m = s*BATCH+b, n = h*64+d
// g_mask: fp16 copy of the additive mask (halves attn mask traffic).
// ---------------------------------------------------------------------------
__device__ __align__(16) __half g_x[MROWS * HID];
__device__ __align__(16) __half g_w[3 * HID * HID];
__device__ __align__(16) __half g_q[MROWS * HID];
__device__ __align__(16) __half g_k[MROWS * HID];
__device__ __align__(16) __half g_v[MROWS * HID];
__device__ __align__(16) __half g_mask[BATCH * SEQ * SEQ];

// ---------------------------------------------------------------------------
// Helpers
// ---------------------------------------------------------------------------
__device__ __forceinline__ void mma16816(float* d, const uint32_t* a,
                                         const uint32_t* b) {
    asm volatile(
        "mma.sync.aligned.m16n8k16.row.col.f32.f16.f16.f32 "
        "{%0,%1,%2,%3}, {%4,%5,%6,%7}, {%8,%9}, {%0,%1,%2,%3};"
        : "+f"(d[0]), "+f"(d[1]), "+f"(d[2]), "+f"(d[3])
        : "r"(a[0]), "r"(a[1]), "r"(a[2]), "r"(a[3]),
          "r"(b[0]), "r"(b[1]));
}

__device__ __forceinline__ uint32_t h2pack(float x, float y) {
    __half2 t = __float22half2_rn(make_float2(x, y));
    return *(uint32_t*)&t;
}

// ---------------------------------------------------------------------------
// Fused convert: fp32 -> fp16 for X, Wq, Wk, Wv, and the mask.
// Static block partition: [0,1024) X; [1024,1792) Wq/Wk/Wv (256 each);
// [1792,2816) mask (4M floats = 1M float4 = 1024 blocks).
// Each block: 256 threads x 4 float4 = 1024 float4.
// ---------------------------------------------------------------------------
__global__ void split_all(const float4* __restrict__ X,
                          const float4* __restrict__ Wq,
                          const float4* __restrict__ Wk,
                          const float4* __restrict__ Wv,
                          const float4* __restrict__ M)
{
    const int bidx = blockIdx.x;
    const float4* src;
    __half* dst;
    int base;
    if (bidx < 1024) {
        src = X; dst = g_x; base = bidx * 1024;
    } else if (bidx < 1792) {
        const int r   = (bidx - 1024) >> 8;
        const int off = (bidx - 1024) & 255;
        src = (r == 0) ? Wq : (r == 1) ? Wk : Wv;
        dst = g_w + (size_t)r * HID * HID;
        base = off * 1024;
    } else {
        src = M; dst = g_mask; base = (bidx - 1792) * 1024;
    }
    const int i0 = base + threadIdx.x;
    #pragma unroll
    for (int u = 0; u < 4; u++) {
        const int i = i0 + u * 256;
        float4 v = src[i];
        uint2 hv;
        hv.x = h2pack(v.x, v.y);
        hv.y = h2pack(v.z, v.w);
        ((uint2*)dst)[i] = hv;
    }
}

// ---------------------------------------------------------------------------
// fp16 GEMM via mma.sync (R12 exact): C = X @ W^T + b -> fp16.
// CTA tile 128x128, 8 warps (32M x 64N), K-chunk 64, serialized loads.
// grid = (HID/128, MROWS/128, 3), block = 256.
// ---------------------------------------------------------------------------
#define TROW   72                      // halves per smem row (64 data + 8 pad)
#define TWORDS (128 * (TROW / 2))      // 4608 words per tile
#define GEMM_SMEM (2 * 128 * TROW * 2) // 36864 B

__global__ __launch_bounds__(256) void gemm_kernel(
    const float* __restrict__ b0,
    const float* __restrict__ b1,
    const float* __restrict__ b2)
{
    extern __shared__ __align__(16) __half sm[];
    __half* tA = sm;
    __half* tB = sm + 128 * TROW;
    const uint32_t* smw = (const uint32_t*)sm;

    const int tid  = threadIdx.x;
    const int wid  = tid >> 5;
    const int lane = tid & 31;
    const int g    = lane >> 2;
    const int cq   = lane & 3;

    const int n0 = blockIdx.x * 128;
    const int m0 = blockIdx.y * 128;
    const int z  = blockIdx.z;

    const __half* W = g_w + (size_t)z * HID * HID;
    const float* bias = (z == 0) ? b0 : (z == 1) ? b1 : b2;
    __half* dst = (z == 0) ? g_q : (z == 1) ? g_k : g_v;

    const int wm = (wid & 3) * 32;
    const int wn = (wid >> 2) * 64;

    float acc[2][8][4];
    #pragma unroll
    for (int mi = 0; mi < 2; mi++)
        #pragma unroll
        for (int nj = 0; nj < 8; nj++)
            #pragma unroll
            for (int r = 0; r < 4; r++) acc[mi][nj][r] = 0.f;

    const int lrow = tid >> 3;            // 0..31 (row within pass)
    const int lcol = (tid & 7) * 8;       // half offset within row

    for (int c = 0; c < HID / 64; c++) {
        const int k0 = c * 64;
        #pragma unroll
        for (int rr = 0; rr < 128; rr += 32) {
            const int row = rr + lrow;
            *(float4*)&tA[row * TROW + lcol] =
                *(const float4*)&g_x[(size_t)(m0 + row) * HID + k0 + lcol];
            *(float4*)&tB[row * TROW + lcol] =
                *(const float4*)&W[(size_t)(n0 + row) * HID + k0 + lcol];
        }
        __syncthreads();

        #pragma unroll
        for (int ks = 0; ks < 4; ks++) {
            uint32_t ah[2][4];
            #pragma unroll
            for (int mi = 0; mi < 2; mi++) {
                const int base = (wm + mi * 16 + g) * (TROW / 2) + ks * 8 + cq;
                ah[mi][0] = smw[base];
                ah[mi][1] = smw[base + 8 * (TROW / 2)];
                ah[mi][2] = smw[base + 4];
                ah[mi][3] = smw[base + 8 * (TROW / 2) + 4];
            }
            #pragma unroll
            for (int nj = 0; nj < 8; nj++) {
                const int bbase = TWORDS + (wn + nj * 8 + g) * (TROW / 2) + ks * 8 + cq;
                uint32_t bh[2];
                bh[0] = smw[bbase];
                bh[1] = smw[bbase + 4];
                #pragma unroll
                for (int mi = 0; mi < 2; mi++)
                    mma16816(acc[mi][nj], ah[mi], bh);
            }
        }
        __syncthreads();
    }

    // Epilogue: add bias, convert to fp16
    #pragma unroll
    for (int mi = 0; mi < 2; mi++) {
        const int r0 = m0 + wm + mi * 16 + g;
        #pragma unroll
        for (int nj = 0; nj < 8; nj++) {
            const int col = n0 + wn + nj * 8 + cq * 2;
            const float bz0 = __ldg(&bias[col]);
            const float bz1 = __ldg(&bias[col + 1]);
            *(uint32_t*)&dst[(size_t)r0 * HID + col] =
                h2pack(acc[mi][nj][0] + bz0, acc[mi][nj][1] + bz1);
            *(uint32_t*)&dst[(size_t)(r0 + 8) * HID + col] =
                h2pack(acc[mi][nj][2] + bz0, acc[mi][nj][3] + bz1);
        }
    }
}

// ---------------------------------------------------------------------------
// fp16 tensor-core flash attention (R12 structure; mask reads now fp16).
// grid = (SEQ/128, B*H), block = 256 (8 warps, 16 query rows each).
// ---------------------------------------------------------------------------
#define KROWW  36                          // words per K row (72 halves)
#define KTILE_W (128 * KROWW)              // 4608 words
#define VROWW  68                          // words per Vt row (136 halves)
#define VT_OFF KTILE_W
#define ATTN_SMEM ((KTILE_W + 64 * VROWW) * 4)   // 35840 B

__global__ __launch_bounds__(256) void attn_kernel(float* __restrict__ out)
{
    extern __shared__ __align__(16) uint32_t smw[];
    uint16_t* smh = (uint16_t*)smw;

    const int tid  = threadIdx.x;
    const int wid  = tid >> 5;
    const int lane = tid & 31;
    const int g    = lane >> 2;
    const int cq   = lane & 3;
    const int bh   = blockIdx.y;
    const int b    = bh >> 4;
    const int h    = bh & 15;
    const int q0   = blockIdx.x * 128;

    const int lrow = tid >> 3;
    const int lcol = (tid & 7) * 8;

    // ---- Stage Q (128x64) through K region; keep fragments in registers
    #pragma unroll
    for (int rr = 0; rr < 128; rr += 32) {
        const int r = rr + lrow;
        const size_t off = ((size_t)(q0 + r) * BATCH + b) * HID + h * DH + lcol;
        *(uint4*)(smh + r * 72 + lcol) = *(const uint4*)(g_q + off);
    }
    __syncthreads();

    uint32_t qh[4][4];
    #pragma unroll
    for (int ks = 0; ks < 4; ks++) {
        const int base = (wid * 16 + g) * KROWW + ks * 8 + cq;
        qh[ks][0] = smw[base];
        qh[ks][1] = smw[base + 8 * KROWW];
        qh[ks][2] = smw[base + 4];
        qh[ks][3] = smw[base + 8 * KROWW + 4];
    }

    float m0 = -1e30f, m1 = -1e30f, l0 = 0.f, l1 = 0.f;
    float oacc[8][4];
    #pragma unroll
    for (int j = 0; j < 8; j++)
        #pragma unroll
        for (int r = 0; r < 4; r++) oacc[j][r] = 0.f;

    const float scale = 0.125f;           // 1/sqrt(64)
    const int r0 = q0 + wid * 16 + g;     // query rows r0, r0+8
    const __half* mrow0 = g_mask + (size_t)b * SEQ * SEQ + (size_t)r0 * SEQ;
    const __half* mrow1 = mrow0 + 8 * (size_t)SEQ;

    const int vp  = tid & 63;             // key pair (keys 2vp, 2vp+1)
    const int vd0 = (tid >> 6) * 16;      // 16 d-values per thread

    for (int k0 = 0; k0 < SEQ; k0 += 128) {
        __syncthreads();                  // previous S/PV readers done

        // --- K tile (128 keys x 64 d)
        #pragma unroll
        for (int rr = 0; rr < 128; rr += 32) {
            const int kk = rr + lrow;
            const size_t off = ((size_t)(k0 + kk) * BATCH + b) * HID + h * DH + lcol;
            *(uint4*)(smh + kk * 72 + lcol) = *(const uint4*)(g_k + off);
        }
        // --- V tile transposed: Vt[d][key]
        {
            const size_t ra = ((size_t)(k0 + 2 * vp) * BATCH + b) * HID + h * DH + vd0;
            const size_t rb = ra + BATCH * HID;
            uint4 a0 = *(const uint4*)(g_v + ra);
            uint4 a1 = *(const uint4*)(g_v + ra + 8);
            uint4 c0 = *(const uint4*)(g_v + rb);
            uint4 c1 = *(const uint4*)(g_v + rb + 8);
            const uint32_t wa[8] = {a0.x, a0.y, a0.z, a0.w, a1.x, a1.y, a1.z, a1.w};
            const uint32_t wb[8] = {c0.x, c0.y, c0.z, c0.w, c1.x, c1.y, c1.z, c1.w};
            #pragma unroll
            for (int j = 0; j < 8; j++) {
                smw[VT_OFF + (vd0 + 2 * j)     * VROWW + vp] = __byte_perm(wa[j], wb[j], 0x5410);
                smw[VT_OFF + (vd0 + 2 * j + 1) * VROWW + vp] = __byte_perm(wa[j], wb[j], 0x7632);
            }
        }
        __syncthreads();

        // --- S = Q K^T (16 n-tiles of 8 keys)
        float sa[16][4];
        #pragma unroll
        for (int nt = 0; nt < 16; nt++) {
            sa[nt][0] = 0.f; sa[nt][1] = 0.f; sa[nt][2] = 0.f; sa[nt][3] = 0.f;
            #pragma unroll
            for (int ks = 0; ks < 4; ks++) {
                const int ba = (nt * 8 + g) * KROWW + ks * 8 + cq;
                uint32_t bf[2];
                bf[0] = smw[ba];
                bf[1] = smw[ba + 4];
                mma16816(sa[nt], qh[ks], bf);
            }
        }

        // --- scale + mask (fp16 pairs) + row max
        float nx0 = -1e30f, nx1 = -1e30f;
        #pragma unroll
        for (int nt = 0; nt < 16; nt++) {
            const __half2 mh0 = *(const __half2*)&mrow0[k0 + nt * 8 + 2 * cq];
            const __half2 mh1 = *(const __half2*)&mrow1[k0 + nt * 8 + 2 * cq];
            const float2 mv0 = __half22float2(mh0);
            const float2 mv1 = __half22float2(mh1);
            sa[nt][0] = fmaf(sa[nt][0], scale, mv0.x);
            sa[nt][1] = fmaf(sa[nt][1], scale, mv0.y);
            sa[nt][2] = fmaf(sa[nt][2], scale, mv1.x);
            sa[nt][3] = fmaf(sa[nt][3], scale, mv1.y);
            nx0 = fmaxf(nx0, fmaxf(sa[nt][0], sa[nt][1]));
            nx1 = fmaxf(nx1, fmaxf(sa[nt][2], sa[nt][3]));
        }
        nx0 = fmaxf(nx0, __shfl_xor_sync(0xffffffffu, nx0, 1));
        nx0 = fmaxf(nx0, __shfl_xor_sync(0xffffffffu, nx0, 2));
        nx1 = fmaxf(nx1, __shfl_xor_sync(0xffffffffu, nx1, 1));
        nx1 = fmaxf(nx1, __shfl_xor_sync(0xffffffffu, nx1, 2));

        const float mn0 = fmaxf(m0, nx0), mn1 = fmaxf(m1, nx1);
        const float c0s = __expf(m0 - mn0), c1s = __expf(m1 - mn1);
        m0 = mn0; m1 = mn1;
        l0 *= c0s; l1 *= c1s;
        #pragma unroll
        for (int j = 0; j < 8; j++) {
            oacc[j][0] *= c0s; oacc[j][1] *= c0s;
            oacc[j][2] *= c1s; oacc[j][3] *= c1s;
        }

        // --- P (fp16) and PV, per 16-key k-step
        #pragma unroll
        for (int kt = 0; kt < 8; kt++) {
            const float p00 = __expf(sa[2 * kt][0] - m0);
            const float p01 = __expf(sa[2 * kt][1] - m0);
            const float p10 = __expf(sa[2 * kt][2] - m1);
            const float p11 = __expf(sa[2 * kt][3] - m1);
            const float p20 = __expf(sa[2 * kt + 1][0] - m0);
            const float p21 = __expf(sa[2 * kt + 1][1] - m0);
            const float p30 = __expf(sa[2 * kt + 1][2] - m1);
            const float p31 = __expf(sa[2 * kt + 1][3] - m1);
            l0 += p00 + p01 + p20 + p21;
            l1 += p10 + p11 + p30 + p31;

            uint32_t pa[4];
            pa[0] = h2pack(p00, p01);
            pa[1] = h2pack(p10, p11);
            pa[2] = h2pack(p20, p21);
            pa[3] = h2pack(p30, p31);

            #pragma unroll
            for (int nt2 = 0; nt2 < 8; nt2++) {
                const int ba = VT_OFF + (nt2 * 8 + g) * VROWW + kt * 8 + cq;
                uint32_t vf[2];
                vf[0] = smw[ba];
                vf[1] = smw[ba + 4];
                mma16816(oacc[nt2], pa, vf);
            }
        }
    }

    // --- reduce l across the 4 lanes per row, normalize, store (S,B,HID)
    l0 += __shfl_xor_sync(0xffffffffu, l0, 1);
    l0 += __shfl_xor_sync(0xffffffffu, l0, 2);
    l1 += __shfl_xor_sync(0xffffffffu, l1, 1);
    l1 += __shfl_xor_sync(0xffffffffu, l1, 2);
    const float i0 = 1.0f / l0, i1 = 1.0f / l1;

    #pragma unroll
    for (int nt2 = 0; nt2 < 8; nt2++) {
        const int col = h * DH + nt2 * 8 + 2 * cq;
        const size_t o0 = (size_t)r0 * (BATCH * HID) + (size_t)b * HID + col;
        const size_t o1 = o0 + 8 * (size_t)(BATCH * HID);
        float2 v0, v1;
        v0.x = oacc[nt2][0] * i0; v0.y = oacc[nt2][1] * i0;
        v1.x = oacc[nt2][2] * i1; v1.y = oacc[nt2][3] * i1;
        *(float2*)&out[o0] = v0;
        *(float2*)&out[o1] = v1;
    }
}

// ---------------------------------------------------------------------------
// Launch
// ---------------------------------------------------------------------------
extern "C" void kernel_launch(void* const* d_in, const int* in_sizes, int n_in,
                              void* d_out, int out_size)
{
    const float* X    = (const float*)d_in[0];
    const float* mask = (const float*)d_in[1];
    const float* Wq   = (const float*)d_in[2];
    const float* bq   = (const float*)d_in[3];
    const float* Wk   = (const float*)d_in[4];
    const float* bk   = (const float*)d_in[5];
    const float* Wv   = (const float*)d_in[6];
    const float* bv   = (const float*)d_in[7];
    float* out = (float*)d_out;

    split_all<<<2816, 256>>>((const float4*)X, (const float4*)Wq,
                             (const float4*)Wk, (const float4*)Wv,
                             (const float4*)mask);

    cudaFuncSetAttribute(gemm_kernel,
                         cudaFuncAttributeMaxDynamicSharedMemorySize, GEMM_SMEM);
    dim3 ggrid(HID / 128, MROWS / 128, 3);
    gemm_kernel<<<ggrid, 256, GEMM_SMEM>>>(bq, bk, bv);

    cudaFuncSetAttribute(attn_kernel,
                         cudaFuncAttributeMaxDynamicSharedMemorySize, ATTN_SMEM);
    dim3 agrid(SEQ / 128, BHTOT);
    attn_kernel<<<agrid, 256, ATTN_SMEM>>>(out);
}

// round 17
// speedup vs baseline: 1.2313x; 1.0607x over previous
#include <cuda_runtime.h>
#include <cuda_fp16.h>
#include <cstdint>

#define HID    1024
#define SEQ    1024
#define BATCH  4
#define NHEADS 16
#define DH     64
#define MROWS  (SEQ * BATCH)      // 4096
#define BHTOT  (BATCH * NHEADS)   // 64

// ---------------------------------------------------------------------------
// Device scratch (static -> allocation-guard safe). fp16 copies.
// ---------------------------------------------------------------------------
__device__ __align__(16) __half g_x[MROWS * HID];
__device__ __align__(16) __half g_w[3 * HID * HID];
__device__ __align__(16) __half g_q[MROWS * HID];
__device__ __align__(16) __half g_k[MROWS * HID];
__device__ __align__(16) __half g_v[MROWS * HID];
__device__ __align__(16) __half g_mask[BATCH * SEQ * SEQ];

// ---------------------------------------------------------------------------
// Helpers
// ---------------------------------------------------------------------------
__device__ __forceinline__ void mma16816(float* d, const uint32_t* a,
                                         const uint32_t* b) {
    asm volatile(
        "mma.sync.aligned.m16n8k16.row.col.f32.f16.f16.f32 "
        "{%0,%1,%2,%3}, {%4,%5,%6,%7}, {%8,%9}, {%0,%1,%2,%3};"
        : "+f"(d[0]), "+f"(d[1]), "+f"(d[2]), "+f"(d[3])
        : "r"(a[0]), "r"(a[1]), "r"(a[2]), "r"(a[3]),
          "r"(b[0]), "r"(b[1]));
}

__device__ __forceinline__ void ldsm_x4(uint32_t& r0, uint32_t& r1,
                                        uint32_t& r2, uint32_t& r3,
                                        uint32_t addr) {
    asm volatile(
        "ldmatrix.sync.aligned.m8n8.x4.shared.b16 {%0,%1,%2,%3}, [%4];"
        : "=r"(r0), "=r"(r1), "=r"(r2), "=r"(r3) : "r"(addr));
}

__device__ __forceinline__ uint32_t h2pack(float x, float y) {
    __half2 t = __float22half2_rn(make_float2(x, y));
    return *(uint32_t*)&t;
}
__device__ __forceinline__ uint32_t smem_u32(const void* p) {
    uint32_t a;
    asm("{ .reg .u64 t; cvta.to.shared.u64 t, %1; cvt.u32.u64 %0, t; }"
        : "=r"(a) : "l"(p));
    return a;
}

// ---------------------------------------------------------------------------
// Fused convert: fp32 -> fp16 for X, Wq, Wk, Wv, and the mask.
// blocks [0,1024) X; [1024,1792) W's; [1792,2816) mask.
// ---------------------------------------------------------------------------
__global__ void split_all(const float4* __restrict__ X,
                          const float4* __restrict__ Wq,
                          const float4* __restrict__ Wk,
                          const float4* __restrict__ Wv,
                          const float4* __restrict__ M)
{
    const int bidx = blockIdx.x;
    const float4* src;
    __half* dst;
    int base;
    if (bidx < 1024) {
        src = X; dst = g_x; base = bidx * 1024;
    } else if (bidx < 1792) {
        const int r   = (bidx - 1024) >> 8;
        const int off = (bidx - 1024) & 255;
        src = (r == 0) ? Wq : (r == 1) ? Wk : Wv;
        dst = g_w + (size_t)r * HID * HID;
        base = off * 1024;
    } else {
        src = M; dst = g_mask; base = (bidx - 1792) * 1024;
    }
    const int i0 = base + threadIdx.x;
    #pragma unroll
    for (int u = 0; u < 4; u++) {
        const int i = i0 + u * 256;
        float4 v = src[i];
        uint2 hv;
        hv.x = h2pack(v.x, v.y);
        hv.y = h2pack(v.z, v.w);
        ((uint2*)dst)[i] = hv;
    }
}

// ---------------------------------------------------------------------------
// fp16 GEMM via mma.sync + ldmatrix fragment loads.
// CTA tile 128x128, 8 warps (32M x 64N), K-chunk 64, serialized tile loads.
// grid = (HID/128, MROWS/128, 3), block = 256.
// ---------------------------------------------------------------------------
#define TROW   72                      // halves per smem row (64 data + 8 pad)
#define TWORDS (128 * (TROW / 2))      // 4608 words per tile
#define GEMM_SMEM (2 * 128 * TROW * 2) // 36864 B

__global__ __launch_bounds__(256) void gemm_kernel(
    const float* __restrict__ b0p,
    const float* __restrict__ b1p,
    const float* __restrict__ b2p)
{
    extern __shared__ __align__(16) __half sm[];
    __half* tA = sm;
    __half* tB = sm + 128 * TROW;
    const uint32_t smem_base = smem_u32(sm);

    const int tid  = threadIdx.x;
    const int wid  = tid >> 5;
    const int lane = tid & 31;
    const int g    = lane >> 2;
    const int cq   = lane & 3;

    const int n0 = blockIdx.x * 128;
    const int m0 = blockIdx.y * 128;
    const int z  = blockIdx.z;

    const __half* W = g_w + (size_t)z * HID * HID;
    const float* bias = (z == 0) ? b0p : (z == 1) ? b1p : b2p;
    __half* dst = (z == 0) ? g_q : (z == 1) ? g_k : g_v;

    const int wm = (wid & 3) * 32;
    const int wn = (wid >> 2) * 64;

    // ldmatrix lane maps (derived from the verified scalar fragment loads)
    const int a_row  = lane & 15;               // + wm + mi*16
    const int a_ksel = (lane >> 4) * 8;         // halves
    const int b_rowo = ((lane >> 4) * 8) + (lane & 7);
    const int b_ksel = ((lane >> 3) & 1) * 8;   // halves

    float acc[2][8][4];
    #pragma unroll
    for (int mi = 0; mi < 2; mi++)
        #pragma unroll
        for (int nj = 0; nj < 8; nj++)
            #pragma unroll
            for (int r = 0; r < 4; r++) acc[mi][nj][r] = 0.f;

    const int lrow = tid >> 3;            // 0..31 (row within pass)
    const int lcol = (tid & 7) * 8;       // half offset within row

    for (int c = 0; c < HID / 64; c++) {
        const int k0 = c * 64;
        #pragma unroll
        for (int rr = 0; rr < 128; rr += 32) {
            const int row = rr + lrow;
            *(float4*)&tA[row * TROW + lcol] =
                *(const float4*)&g_x[(size_t)(m0 + row) * HID + k0 + lcol];
            *(float4*)&tB[row * TROW + lcol] =
                *(const float4*)&W[(size_t)(n0 + row) * HID + k0 + lcol];
        }
        __syncthreads();

        #pragma unroll
        for (int ks = 0; ks < 4; ks++) {
            uint32_t ah[2][4];
            #pragma unroll
            for (int mi = 0; mi < 2; mi++) {
                const uint32_t addr = smem_base +
                    ((wm + mi * 16 + a_row) * TROW + ks * 16 + a_ksel) * 2;
                ldsm_x4(ah[mi][0], ah[mi][1], ah[mi][2], ah[mi][3], addr);
            }
            #pragma unroll
            for (int njp = 0; njp < 4; njp++) {
                uint32_t v0, v1, v2, v3;
                const uint32_t baddr = smem_base + TWORDS * 4 +
                    ((wn + njp * 16 + b_rowo) * TROW + ks * 16 + b_ksel) * 2;
                ldsm_x4(v0, v1, v2, v3, baddr);
                uint32_t bf0[2] = {v0, v1};
                uint32_t bf1[2] = {v2, v3};
                #pragma unroll
                for (int mi = 0; mi < 2; mi++) {
                    mma16816(acc[mi][2 * njp],     ah[mi], bf0);
                    mma16816(acc[mi][2 * njp + 1], ah[mi], bf1);
                }
            }
        }
        __syncthreads();
    }

    // Epilogue: add bias, convert to fp16
    #pragma unroll
    for (int mi = 0; mi < 2; mi++) {
        const int r0 = m0 + wm + mi * 16 + g;
        #pragma unroll
        for (int nj = 0; nj < 8; nj++) {
            const int col = n0 + wn + nj * 8 + cq * 2;
            const float bz0 = __ldg(&bias[col]);
            const float bz1 = __ldg(&bias[col + 1]);
            *(uint32_t*)&dst[(size_t)r0 * HID + col] =
                h2pack(acc[mi][nj][0] + bz0, acc[mi][nj][1] + bz1);
            *(uint32_t*)&dst[(size_t)(r0 + 8) * HID + col] =
                h2pack(acc[mi][nj][2] + bz0, acc[mi][nj][3] + bz1);
        }
    }
}

// ---------------------------------------------------------------------------
// fp16 tensor-core flash attention + ldmatrix fragment loads (fp16 mask).
// grid = (SEQ/128, B*H), block = 256 (8 warps, 16 query rows each).
// ---------------------------------------------------------------------------
#define KROWW  36                          // words per K row (72 halves)
#define KTILE_W (128 * KROWW)              // 4608 words
#define VROWW  68                          // words per Vt row (136 halves)
#define VT_OFF KTILE_W
#define ATTN_SMEM ((KTILE_W + 64 * VROWW) * 4)   // 35840 B

__global__ __launch_bounds__(256) void attn_kernel(float* __restrict__ out)
{
    extern __shared__ __align__(16) uint32_t smw[];
    uint16_t* smh = (uint16_t*)smw;
    const uint32_t smem_base = smem_u32(smw);

    const int tid  = threadIdx.x;
    const int wid  = tid >> 5;
    const int lane = tid & 31;
    const int g    = lane >> 2;
    const int cq   = lane & 3;
    const int bh   = blockIdx.y;
    const int b    = bh >> 4;
    const int h    = bh & 15;
    const int q0   = blockIdx.x * 128;

    const int lrow = tid >> 3;
    const int lcol = (tid & 7) * 8;

    // ldmatrix lane maps
    const int b_rowo = ((lane >> 4) * 8) + (lane & 7);
    const int b_ksel = ((lane >> 3) & 1) * 8;   // halves

    // ---- Stage Q (128x64) through K region; keep fragments in registers
    #pragma unroll
    for (int rr = 0; rr < 128; rr += 32) {
        const int r = rr + lrow;
        const size_t off = ((size_t)(q0 + r) * BATCH + b) * HID + h * DH + lcol;
        *(uint4*)(smh + r * 72 + lcol) = *(const uint4*)(g_q + off);
    }
    __syncthreads();

    uint32_t qh[4][4];
    #pragma unroll
    for (int ks = 0; ks < 4; ks++) {
        const int base = (wid * 16 + g) * KROWW + ks * 8 + cq;
        qh[ks][0] = smw[base];
        qh[ks][1] = smw[base + 8 * KROWW];
        qh[ks][2] = smw[base + 4];
        qh[ks][3] = smw[base + 8 * KROWW + 4];
    }

    float m0 = -1e30f, m1 = -1e30f, l0 = 0.f, l1 = 0.f;
    float oacc[8][4];
    #pragma unroll
    for (int j = 0; j < 8; j++)
        #pragma unroll
        for (int r = 0; r < 4; r++) oacc[j][r] = 0.f;

    const float scale = 0.125f;           // 1/sqrt(64)
    const int r0 = q0 + wid * 16 + g;     // query rows r0, r0+8
    const __half* mrow0 = g_mask + (size_t)b * SEQ * SEQ + (size_t)r0 * SEQ;
    const __half* mrow1 = mrow0 + 8 * (size_t)SEQ;

    const int vp  = tid & 63;             // key pair (keys 2vp, 2vp+1)
    const int vd0 = (tid >> 6) * 16;      // 16 d-values per thread

    for (int k0 = 0; k0 < SEQ; k0 += 128) {
        __syncthreads();                  // previous S/PV readers done

        // --- K tile (128 keys x 64 d)
        #pragma unroll
        for (int rr = 0; rr < 128; rr += 32) {
            const int kk = rr + lrow;
            const size_t off = ((size_t)(k0 + kk) * BATCH + b) * HID + h * DH + lcol;
            *(uint4*)(smh + kk * 72 + lcol) = *(const uint4*)(g_k + off);
        }
        // --- V tile transposed: Vt[d][key]
        {
            const size_t ra = ((size_t)(k0 + 2 * vp) * BATCH + b) * HID + h * DH + vd0;
            const size_t rb = ra + BATCH * HID;
            uint4 a0 = *(const uint4*)(g_v + ra);
            uint4 a1 = *(const uint4*)(g_v + ra + 8);
            uint4 c0 = *(const uint4*)(g_v + rb);
            uint4 c1 = *(const uint4*)(g_v + rb + 8);
            const uint32_t wa[8] = {a0.x, a0.y, a0.z, a0.w, a1.x, a1.y, a1.z, a1.w};
            const uint32_t wb[8] = {c0.x, c0.y, c0.z, c0.w, c1.x, c1.y, c1.z, c1.w};
            #pragma unroll
            for (int j = 0; j < 8; j++) {
                smw[VT_OFF + (vd0 + 2 * j)     * VROWW + vp] = __byte_perm(wa[j], wb[j], 0x5410);
                smw[VT_OFF + (vd0 + 2 * j + 1) * VROWW + vp] = __byte_perm(wa[j], wb[j], 0x7632);
            }
        }
        __syncthreads();

        // --- S = Q K^T via ldmatrix (pairs of 8-key tiles)
        float sa[16][4];
        #pragma unroll
        for (int nt = 0; nt < 16; nt++) {
            sa[nt][0] = 0.f; sa[nt][1] = 0.f; sa[nt][2] = 0.f; sa[nt][3] = 0.f;
        }
        #pragma unroll
        for (int ks = 0; ks < 4; ks++) {
            #pragma unroll
            for (int ntp = 0; ntp < 8; ntp++) {
                uint32_t v0, v1, v2, v3;
                const uint32_t addr = smem_base +
                    ((ntp * 16 + b_rowo) * 72 + ks * 16 + b_ksel) * 2;
                ldsm_x4(v0, v1, v2, v3, addr);
                uint32_t bf0[2] = {v0, v1};
                uint32_t bf1[2] = {v2, v3};
                mma16816(sa[2 * ntp],     qh[ks], bf0);
                mma16816(sa[2 * ntp + 1], qh[ks], bf1);
            }
        }

        // --- scale + mask (fp16 pairs) + row max
        float nx0 = -1e30f, nx1 = -1e30f;
        #pragma unroll
        for (int nt = 0; nt < 16; nt++) {
            const __half2 mh0 = *(const __half2*)&mrow0[k0 + nt * 8 + 2 * cq];
            const __half2 mh1 = *(const __half2*)&mrow1[k0 + nt * 8 + 2 * cq];
            const float2 mv0 = __half22float2(mh0);
            const float2 mv1 = __half22float2(mh1);
            sa[nt][0] = fmaf(sa[nt][0], scale, mv0.x);
            sa[nt][1] = fmaf(sa[nt][1], scale, mv0.y);
            sa[nt][2] = fmaf(sa[nt][2], scale, mv1.x);
            sa[nt][3] = fmaf(sa[nt][3], scale, mv1.y);
            nx0 = fmaxf(nx0, fmaxf(sa[nt][0], sa[nt][1]));
            nx1 = fmaxf(nx1, fmaxf(sa[nt][2], sa[nt][3]));
        }
        nx0 = fmaxf(nx0, __shfl_xor_sync(0xffffffffu, nx0, 1));
        nx0 = fmaxf(nx0, __shfl_xor_sync(0xffffffffu, nx0, 2));
        nx1 = fmaxf(nx1, __shfl_xor_sync(0xffffffffu, nx1, 1));
        nx1 = fmaxf(nx1, __shfl_xor_sync(0xffffffffu, nx1, 2));

        const float mn0 = fmaxf(m0, nx0), mn1 = fmaxf(m1, nx1);
        const float c0s = __expf(m0 - mn0), c1s = __expf(m1 - mn1);
        m0 = mn0; m1 = mn1;
        l0 *= c0s; l1 *= c1s;
        #pragma unroll
        for (int j = 0; j < 8; j++) {
            oacc[j][0] *= c0s; oacc[j][1] *= c0s;
            oacc[j][2] *= c1s; oacc[j][3] *= c1s;
        }

        // --- P (fp16) and PV via ldmatrix, per 16-key k-step
        #pragma unroll
        for (int kt = 0; kt < 8; kt++) {
            const float p00 = __expf(sa[2 * kt][0] - m0);
            const float p01 = __expf(sa[2 * kt][1] - m0);
            const float p10 = __expf(sa[2 * kt][2] - m1);
            const float p11 = __expf(sa[2 * kt][3] - m1);
            const float p20 = __expf(sa[2 * kt + 1][0] - m0);
            const float p21 = __expf(sa[2 * kt + 1][1] - m0);
            const float p30 = __expf(sa[2 * kt + 1][2] - m1);
            const float p31 = __expf(sa[2 * kt + 1][3] - m1);
            l0 += p00 + p01 + p20 + p21;
            l1 += p10 + p11 + p30 + p31;

            uint32_t pa[4];
            pa[0] = h2pack(p00, p01);
            pa[1] = h2pack(p10, p11);
            pa[2] = h2pack(p20, p21);
            pa[3] = h2pack(p30, p31);

            #pragma unroll
            for (int np = 0; np < 4; np++) {
                uint32_t v0, v1, v2, v3;
                const uint32_t addr = smem_base + VT_OFF * 4 +
                    ((np * 16 + b_rowo) * 136 + kt * 16 + b_ksel) * 2;
                ldsm_x4(v0, v1, v2, v3, addr);
                uint32_t vf0[2] = {v0, v1};
                uint32_t vf1[2] = {v2, v3};
                mma16816(oacc[2 * np],     pa, vf0);
                mma16816(oacc[2 * np + 1], pa, vf1);
            }
        }
    }

    // --- reduce l across the 4 lanes per row, normalize, store (S,B,HID)
    l0 += __shfl_xor_sync(0xffffffffu, l0, 1);
    l0 += __shfl_xor_sync(0xffffffffu, l0, 2);
    l1 += __shfl_xor_sync(0xffffffffu, l1, 1);
    l1 += __shfl_xor_sync(0xffffffffu, l1, 2);
    const float i0 = 1.0f / l0, i1 = 1.0f / l1;

    #pragma unroll
    for (int nt2 = 0; nt2 < 8; nt2++) {
        const int col = h * DH + nt2 * 8 + 2 * cq;
        const size_t o0 = (size_t)r0 * (BATCH * HID) + (size_t)b * HID + col;
        const size_t o1 = o0 + 8 * (size_t)(BATCH * HID);
        float2 v0, v1;
        v0.x = oacc[nt2][0] * i0; v0.y = oacc[nt2][1] * i0;
        v1.x = oacc[nt2][2] * i1; v1.y = oacc[nt2][3] * i1;
        *(float2*)&out[o0] = v0;
        *(float2*)&out[o1] = v1;
    }
}

// ---------------------------------------------------------------------------
// Launch
// ---------------------------------------------------------------------------
extern "C" void kernel_launch(void* const* d_in, const int* in_sizes, int n_in,
                              void* d_out, int out_size)
{
    const float* X    = (const float*)d_in[0];
    const float* mask = (const float*)d_in[1];
    const float* Wq   = (const float*)d_in[2];
    const float* bq   = (const float*)d_in[3];
    const float* Wk   = (const float*)d_in[4];
    const float* bk   = (const float*)d_in[5];
    const float* Wv   = (const float*)d_in[6];
    const float* bv   = (const float*)d_in[7];
    float* out = (float*)d_out;

    split_all<<<2816, 256>>>((const float4*)X, (const float4*)Wq,
                             (const float4*)Wk, (const float4*)Wv,
                             (const float4*)mask);

    cudaFuncSetAttribute(gemm_kernel,
                         cudaFuncAttributeMaxDynamicSharedMemorySize, GEMM_SMEM);
    dim3 ggrid(HID / 128, MROWS / 128, 3);
    gemm_kernel<<<ggrid, 256, GEMM_SMEM>>>(bq, bk, bv);

    cudaFuncSetAttribute(attn_kernel,
                         cudaFuncAttributeMaxDynamicSharedMemorySize, ATTN_SMEM);
    dim3 agrid(SEQ / 128, BHTOT);
    attn_kernel<<<agrid, 256, ATTN_SMEM>>>(out);
}